// round 1
// baseline (speedup 1.0000x reference)
#include <cuda_runtime.h>

#define T_ 1024
#define B_ 128

// ---------------- scratch (device globals; no allocations) ----------------
__device__ int   g_chars[B_*T_];                 // argmax indices, [b][t]
__device__ float g_w1t[3*400*128];               // w1 transposed [k][ci][co]
__device__ float g_w2t[3*128*64];
__device__ float g_w3t[3*64*32];
__device__ float g_gpart[B_*3*128];              // g_style contribution per (b,k,co)
__device__ float g_sty[B_*80*3*128];             // stylepre [b][char][k][co]
__device__ float g_x1[B_*T_*128];                // conv1 out (pre-GN), [b][t][c]
__device__ float g_x2[B_*T_*64];
__device__ float g_x3[B_*T_*32];
__device__ float g_ab1[B_*128], g_dd1[B_*128];   // GN fused affine: relu(a*x+d)
__device__ float g_ab2[B_*64],  g_dd2[B_*64];
__device__ float g_ab3[B_*32],  g_dd3[B_*32];

// ---------------- weight transpose: w[O][I][3] -> wt[k][I][O] ----------------
__global__ void wtrans_k(const float* __restrict__ w, int O, int I, int which) {
    float* wt = (which == 0) ? g_w1t : (which == 1) ? g_w2t : g_w3t;
    int idx = blockIdx.x * blockDim.x + threadIdx.x;
    int total = O * I * 3;
    if (idx < total) {
        int k = idx % 3;
        int i = (idx / 3) % I;
        int o = idx / (3 * I);
        wt[(k * I + i) * O + o] = w[idx];
    }
}

// ---------------- argmax over 80 classes, warp per (t,b) ----------------
__global__ void argmax_k(const float* __restrict__ inp) {
    int gw = (blockIdx.x * blockDim.x + threadIdx.x) >> 5;
    int lane = threadIdx.x & 31;
    if (gw >= T_ * B_) return;
    int t = gw >> 7;          // / B_
    int b = gw & 127;         // % B_
    const float* row = inp + (t * B_ + b) * 80;
    float best = -3.4e38f;
    int bi = 0;
    for (int c = lane; c < 80; c += 32) {
        float v = row[c];
        if (v > best) { best = v; bi = c; }
    }
    for (int off = 16; off; off >>= 1) {
        float ov = __shfl_down_sync(0xFFFFFFFFu, best, off);
        int   oi = __shfl_down_sync(0xFFFFFFFFu, bi, off);
        if (ov > best || (ov == best && oi < bi)) { best = ov; bi = oi; }
    }
    bi = __shfl_sync(0xFFFFFFFFu, bi, 0);
    if (lane == 0) g_chars[b * T_ + t] = bi;
}

// ---------------- stylepre[b][c][k][co] = sum_ci char_style[b,c,ci]*w1[co,336+ci,k] ----------------
__global__ void stylepre_k(const float* __restrict__ char_style) {
    __shared__ float sw[64 * 128];   // [ci][co] for this k
    int k = blockIdx.x, b = blockIdx.y, co = threadIdx.x;
    int base = (k * 400 + 336) * 128;
    for (int i = threadIdx.x; i < 64 * 128; i += 128) sw[i] = g_w1t[base + i];
    __syncthreads();
    for (int c = 0; c < 80; c++) {
        const float* cs = char_style + (b * 80 + c) * 64;
        float a = 0.f;
        #pragma unroll 8
        for (int ci = 0; ci < 64; ci++) a = fmaf(cs[ci], sw[ci * 128 + co], a);
        g_sty[((b * 80 + c) * 3 + k) * 128 + co] = a;
    }
}

// ---------------- gpart[b][k][co] = sum_ci g_style[b,ci]*w1[co,80+ci,k] ----------------
__global__ void gpart_k(const float* __restrict__ g_style) {
    __shared__ float sg[256];
    int b = blockIdx.x, co = threadIdx.x;
    for (int i = co; i < 256; i += 128) sg[i] = g_style[b * 256 + i];
    __syncthreads();
    float a0 = 0.f, a1 = 0.f, a2 = 0.f;
    for (int ci = 0; ci < 256; ci++) {
        float v = sg[ci];
        a0 = fmaf(v, g_w1t[(0 * 400 + 80 + ci) * 128 + co], a0);
        a1 = fmaf(v, g_w1t[(1 * 400 + 80 + ci) * 128 + co], a1);
        a2 = fmaf(v, g_w1t[(2 * 400 + 80 + ci) * 128 + co], a2);
    }
    g_gpart[(b * 3 + 0) * 128 + co] = a0;
    g_gpart[(b * 3 + 1) * 128 + co] = a1;
    g_gpart[(b * 3 + 2) * 128 + co] = a2;
}

// ---------------- conv1: only 80 input channels via GEMM; g/style via lookup ----------------
__global__ void conv1_k(const float* __restrict__ inp, const float* __restrict__ bias) {
    int b = blockIdx.y;
    int t0 = blockIdx.x * 16;
    int co = threadIdx.x;
    __shared__ float sx[18][80];
    __shared__ int sch[18];
    for (int i = threadIdx.x; i < 18 * 80; i += 128) {
        int r = i / 80, ci = i % 80;
        int t = t0 - 1 + r;
        sx[r][ci] = (t >= 0 && t < T_) ? inp[(t * B_ + b) * 80 + ci] : 0.f;
    }
    if (threadIdx.x < 18) {
        int t = t0 - 1 + threadIdx.x;
        sch[threadIdx.x] = (t >= 0 && t < T_) ? g_chars[b * T_ + t] : 0;
    }
    __syncthreads();

    float acc[16];
    #pragma unroll
    for (int tt = 0; tt < 16; tt++) acc[tt] = 0.f;

    for (int ci = 0; ci < 80; ci++) {
        float xr[18];
        #pragma unroll
        for (int r = 0; r < 18; r++) xr[r] = sx[r][ci];
        #pragma unroll
        for (int k = 0; k < 3; k++) {
            float w = g_w1t[(k * 400 + ci) * 128 + co];
            #pragma unroll
            for (int tt = 0; tt < 16; tt++) acc[tt] = fmaf(w, xr[tt + k], acc[tt]);
        }
    }

    float bz = bias[co];
    float gp0 = g_gpart[(b * 3 + 0) * 128 + co];
    float gp1 = g_gpart[(b * 3 + 1) * 128 + co];
    float gp2 = g_gpart[(b * 3 + 2) * 128 + co];
    float gp[3] = {gp0, gp1, gp2};
    for (int tt = 0; tt < 16; tt++) {
        int t = t0 + tt;
        float a = acc[tt] + bz;
        #pragma unroll
        for (int k = 0; k < 3; k++) {
            int tp = t + k - 1;
            if (tp >= 0 && tp < T_) {
                a += gp[k] + g_sty[((b * 80 + sch[tt + k]) * 3 + k) * 128 + co];
            }
        }
        g_x1[(b * T_ + t) * 128 + co] = a;
    }
}

// ---------------- GN stats -> fused affine (a, d) for relu(a*x+d) ----------------
template<int C, int G, int WHICH>
__global__ void stats_k(const float* __restrict__ gs, const float* __restrict__ gb) {
    const float* x = (WHICH == 1) ? g_x1 : (WHICH == 2) ? g_x2 : g_x3;
    float* ab = (WHICH == 1) ? g_ab1 : (WHICH == 2) ? g_ab2 : g_ab3;
    float* dd = (WHICH == 1) ? g_dd1 : (WHICH == 2) ? g_dd2 : g_dd3;
    int b = blockIdx.x, c = threadIdx.x;
    const float* p = x + b * T_ * C + c;
    float s = 0.f, q = 0.f;
    for (int t = 0; t < T_; t++) {
        float v = p[t * C];
        s += v;
        q = fmaf(v, v, q);
    }
    __shared__ float ss[C], sq[C];
    ss[c] = s; sq[c] = q;
    __syncthreads();
    int g0 = (c / G) * G;
    float S = 0.f, Q = 0.f;
    #pragma unroll
    for (int j = 0; j < G; j++) { S += ss[g0 + j]; Q += sq[g0 + j]; }
    float n = (float)(G * T_);
    float mu = S / n;
    float var = Q / n - mu * mu;
    float a = rsqrtf(var + 1e-5f) * gs[c];
    ab[b * C + c] = a;
    dd[b * C + c] = gb[c] - mu * a;
}

// ---------------- conv2: 128->64, GN1+relu applied on smem load ----------------
__global__ void conv2_k(const float* __restrict__ bias) {
    int b = blockIdx.y;
    int t0 = blockIdx.x * 32;
    int co = threadIdx.x;       // 0..63
    int ty = threadIdx.y;       // 0..3
    __shared__ float sx[34][128];
    int tid = ty * 64 + co;
    for (int i = tid; i < 34 * 128; i += 256) {
        int r = i >> 7, ci = i & 127;
        int t = t0 - 1 + r;
        float v = 0.f;
        if (t >= 0 && t < T_) {
            float a = g_ab1[b * 128 + ci], d0 = g_dd1[b * 128 + ci];
            v = fmaxf(fmaf(a, g_x1[(b * T_ + t) * 128 + ci], d0), 0.f);
        }
        sx[r][ci] = v;
    }
    __syncthreads();
    int rbase = ty * 8;
    float acc[8];
    #pragma unroll
    for (int tt = 0; tt < 8; tt++) acc[tt] = 0.f;
    for (int ci = 0; ci < 128; ci++) {
        float xr[10];
        #pragma unroll
        for (int r = 0; r < 10; r++) xr[r] = sx[rbase + r][ci];
        #pragma unroll
        for (int k = 0; k < 3; k++) {
            float w = g_w2t[(k * 128 + ci) * 64 + co];
            #pragma unroll
            for (int tt = 0; tt < 8; tt++) acc[tt] = fmaf(w, xr[tt + k], acc[tt]);
        }
    }
    float bz = bias[co];
    #pragma unroll
    for (int tt = 0; tt < 8; tt++) {
        int t = t0 + rbase + tt;
        g_x2[(b * T_ + t) * 64 + co] = acc[tt] + bz;
    }
}

// ---------------- conv3: 64->32 ----------------
__global__ void conv3_k(const float* __restrict__ bias) {
    int b = blockIdx.y;
    int t0 = blockIdx.x * 32;
    int co = threadIdx.x;       // 0..31
    int ty = threadIdx.y;       // 0..7
    __shared__ float sx[34][64];
    int tid = ty * 32 + co;
    for (int i = tid; i < 34 * 64; i += 256) {
        int r = i >> 6, ci = i & 63;
        int t = t0 - 1 + r;
        float v = 0.f;
        if (t >= 0 && t < T_) {
            float a = g_ab2[b * 64 + ci], d0 = g_dd2[b * 64 + ci];
            v = fmaxf(fmaf(a, g_x2[(b * T_ + t) * 64 + ci], d0), 0.f);
        }
        sx[r][ci] = v;
    }
    __syncthreads();
    int rbase = ty * 4;
    float acc[4] = {0.f, 0.f, 0.f, 0.f};
    for (int ci = 0; ci < 64; ci++) {
        float xr[6];
        #pragma unroll
        for (int r = 0; r < 6; r++) xr[r] = sx[rbase + r][ci];
        #pragma unroll
        for (int k = 0; k < 3; k++) {
            float w = g_w3t[(k * 64 + ci) * 32 + co];
            #pragma unroll
            for (int tt = 0; tt < 4; tt++) acc[tt] = fmaf(w, xr[tt + k], acc[tt]);
        }
    }
    float bz = bias[co];
    #pragma unroll
    for (int tt = 0; tt < 4; tt++) {
        int t = t0 + rbase + tt;
        g_x3[(b * T_ + t) * 32 + co] = acc[tt] + bz;
    }
}

// ---------------- final: GN3+relu + 1x1 conv + affine, write (T,B,1) ----------------
__global__ void final_k(const float* __restrict__ w4, const float* __restrict__ b4,
                        const float* __restrict__ mean, const float* __restrict__ stdv,
                        float* __restrict__ out) {
    int b = blockIdx.x;
    __shared__ float sw4[32], sa[32], sd[32];
    if (threadIdx.x < 32) {
        sw4[threadIdx.x] = w4[threadIdx.x];
        sa[threadIdx.x] = g_ab3[b * 32 + threadIdx.x];
        sd[threadIdx.x] = g_dd3[b * 32 + threadIdx.x];
    }
    __syncthreads();
    float bb = b4[0], me = mean[0], sc = stdv[0];
    for (int t = threadIdx.x; t < T_; t += blockDim.x) {
        const float* p = g_x3 + (b * T_ + t) * 32;
        float a = bb;
        #pragma unroll
        for (int ci = 0; ci < 32; ci++) {
            float v = fmaxf(fmaf(sa[ci], p[ci], sd[ci]), 0.f);
            a = fmaf(sw4[ci], v, a);
        }
        out[t * B_ + b] = fmaf(a, sc, me);
    }
}

// ---------------- launcher ----------------
extern "C" void kernel_launch(void* const* d_in, const int* in_sizes, int n_in,
                              void* d_out, int out_size) {
    (void)in_sizes; (void)n_in; (void)out_size;
    const float* input      = (const float*)d_in[0];
    const float* g_style    = (const float*)d_in[1];
    // d_in[2] spacing_style: unused by reference
    const float* char_style = (const float*)d_in[3];
    const float* w1 = (const float*)d_in[4];
    const float* b1 = (const float*)d_in[5];
    const float* gs1 = (const float*)d_in[6];
    const float* gb1 = (const float*)d_in[7];
    const float* w2 = (const float*)d_in[8];
    const float* b2 = (const float*)d_in[9];
    const float* gs2 = (const float*)d_in[10];
    const float* gb2 = (const float*)d_in[11];
    const float* w3 = (const float*)d_in[12];
    const float* b3 = (const float*)d_in[13];
    const float* gs3 = (const float*)d_in[14];
    const float* gb3 = (const float*)d_in[15];
    const float* w4 = (const float*)d_in[16];
    const float* b4 = (const float*)d_in[17];
    const float* mean = (const float*)d_in[18];
    const float* stdv = (const float*)d_in[19];
    float* out = (float*)d_out;

    wtrans_k<<<(128 * 400 * 3 + 255) / 256, 256>>>(w1, 128, 400, 0);
    wtrans_k<<<(64 * 128 * 3 + 255) / 256, 256>>>(w2, 64, 128, 1);
    wtrans_k<<<(32 * 64 * 3 + 255) / 256, 256>>>(w3, 32, 64, 2);
    argmax_k<<<(T_ * B_ * 32) / 256, 256>>>(input);
    stylepre_k<<<dim3(3, B_), 128>>>(char_style);
    gpart_k<<<B_, 128>>>(g_style);
    conv1_k<<<dim3(T_ / 16, B_), 128>>>(input, b1);
    stats_k<128, 4, 1><<<B_, 128>>>(gs1, gb1);
    conv2_k<<<dim3(T_ / 32, B_), dim3(64, 4)>>>(b2);
    stats_k<64, 2, 2><<<B_, 64>>>(gs2, gb2);
    conv3_k<<<dim3(T_ / 32, B_), dim3(32, 8)>>>(b3);
    stats_k<32, 1, 3><<<B_, 32>>>(gs3, gb3);
    final_k<<<B_, 256>>>(w4, b4, mean, stdv, out);
}

// round 3
// speedup vs baseline: 1.2766x; 1.2766x over previous
#include <cuda_runtime.h>

#define T_ 1024
#define B_ 128
typedef unsigned long long ull;

// ---------------- packed f32x2 helpers (Blackwell FFMA2) ----------------
__device__ __forceinline__ ull pack2(float v) {
    ull r; unsigned u = __float_as_uint(v);
    asm("mov.b64 %0, {%1, %1};" : "=l"(r) : "r"(u));
    return r;
}
__device__ __forceinline__ void fma2(ull &acc, ull a, ull b) {
    asm("fma.rn.f32x2 %0, %1, %2, %0;" : "+l"(acc) : "l"(a), "l"(b));
}
__device__ __forceinline__ float2 unpack2(ull v) {
    unsigned lo, hi;
    asm("mov.b64 {%0, %1}, %2;" : "=r"(lo), "=r"(hi) : "l"(v));
    return make_float2(__uint_as_float(lo), __uint_as_float(hi));
}

// ---------------- scratch (device globals; no allocations) ----------------
__device__ int   g_chars[B_*T_];
__device__ float g_w1t[3*400*128];               // [k][ci][co]
__device__ float g_w2t[3*128*64];
__device__ float g_w3t[3*64*32];
__device__ float g_gpart[B_*3*128];
__device__ float g_sty[B_*80*3*128];             // [b][char][k][co]
__device__ float g_x1[B_*T_*128];
__device__ float g_x2[B_*T_*64];
__device__ float g_x3[B_*T_*32];
__device__ float g_ab1[B_*128], g_dd1[B_*128];
__device__ float g_ab2[B_*64],  g_dd2[B_*64];
__device__ float g_ab3[B_*32],  g_dd3[B_*32];

// ---------------- weight transpose: w[O][I][3] -> wt[k][I][O] ----------------
__global__ void wtrans_k(const float* __restrict__ w, int O, int I, int which) {
    float* wt = (which == 0) ? g_w1t : (which == 1) ? g_w2t : g_w3t;
    int idx = blockIdx.x * blockDim.x + threadIdx.x;
    int total = O * I * 3;
    if (idx < total) {
        int k = idx % 3;
        int i = (idx / 3) % I;
        int o = idx / (3 * I);
        wt[(k * I + i) * O + o] = w[idx];
    }
}

// ---------------- argmax over 80 classes, warp per (t,b), float4 ----------------
// Tie-break: ALWAYS keep the lowest index (jnp.argmax semantics). The shuffle
// tree needs the explicit (ov == best && oi < bi) arm — fp32 ties DO occur in
// this dataset (~10 expected over 131k rows of 80 normals).
__global__ void argmax_k(const float* __restrict__ inp) {
    int gw = (blockIdx.x * blockDim.x + threadIdx.x) >> 5;
    int lane = threadIdx.x & 31;
    if (gw >= T_ * B_) return;
    int t = gw >> 7;
    int b = gw & 127;
    const float4* row = (const float4*)(inp + (t * B_ + b) * 80);
    float best = -3.4e38f; int bi = 0x7FFFFFFF;
    if (lane < 20) {
        float4 v = row[lane];
        best = v.x; bi = 4 * lane;
        if (v.y > best) { best = v.y; bi = 4 * lane + 1; }
        if (v.z > best) { best = v.z; bi = 4 * lane + 2; }
        if (v.w > best) { best = v.w; bi = 4 * lane + 3; }
    }
    for (int off = 16; off; off >>= 1) {
        float ov = __shfl_down_sync(0xFFFFFFFFu, best, off);
        int   oi = __shfl_down_sync(0xFFFFFFFFu, bi, off);
        if (ov > best || (ov == best && oi < bi)) { best = ov; bi = oi; }
    }
    if (lane == 0) g_chars[b * T_ + t] = bi;
}

// ---------------- stylepre[b][c][k][co] ----------------
__global__ void stylepre_k(const float* __restrict__ char_style) {
    __shared__ float sw[64 * 128];
    int k = blockIdx.x, b = blockIdx.y, co = threadIdx.x;
    int base = (k * 400 + 336) * 128;
    for (int i = threadIdx.x; i < 64 * 128; i += 128) sw[i] = g_w1t[base + i];
    __syncthreads();
    for (int c = 0; c < 80; c++) {
        const float* cs = char_style + (b * 80 + c) * 64;
        float a = 0.f;
        #pragma unroll 8
        for (int ci = 0; ci < 64; ci++) a = fmaf(cs[ci], sw[ci * 128 + co], a);
        g_sty[((b * 80 + c) * 3 + k) * 128 + co] = a;
    }
}

// ---------------- gpart[b][k][co] ----------------
__global__ void gpart_k(const float* __restrict__ g_style) {
    __shared__ float sg[256];
    int b = blockIdx.x, co = threadIdx.x;
    for (int i = co; i < 256; i += 128) sg[i] = g_style[b * 256 + i];
    __syncthreads();
    float a0 = 0.f, a1 = 0.f, a2 = 0.f;
    for (int ci = 0; ci < 256; ci++) {
        float v = sg[ci];
        a0 = fmaf(v, g_w1t[(0 * 400 + 80 + ci) * 128 + co], a0);
        a1 = fmaf(v, g_w1t[(1 * 400 + 80 + ci) * 128 + co], a1);
        a2 = fmaf(v, g_w1t[(2 * 400 + 80 + ci) * 128 + co], a2);
    }
    g_gpart[(b * 3 + 0) * 128 + co] = a0;
    g_gpart[(b * 3 + 1) * 128 + co] = a1;
    g_gpart[(b * 3 + 2) * 128 + co] = a2;
}

// ---------------- conv1: 80-ch GEMM with FFMA2, 2 copairs/thread ----------------
__global__ __launch_bounds__(256) void conv1_k(const float* __restrict__ inp,
                                               const float* __restrict__ bias) {
    int b = blockIdx.y;
    int t0 = blockIdx.x * 64;
    int lane = threadIdx.x;     // 0..31 = copair (co = 2*lane and 64+2*lane)
    int ty = threadIdx.y;       // 0..7
    __shared__ float sx[66][80];
    __shared__ int sch[66];
    int tid = ty * 32 + lane;
    for (int i = tid; i < 66 * 80; i += 256) {
        int r = i / 80, ci = i - r * 80;
        int t = t0 - 1 + r;
        sx[r][ci] = (t >= 0 && t < T_) ? inp[(t * B_ + b) * 80 + ci] : 0.f;
    }
    for (int i = tid; i < 66; i += 256) {
        int t = t0 - 1 + i;
        sch[i] = (t >= 0 && t < T_) ? g_chars[b * T_ + t] : 0;
    }
    __syncthreads();

    int rbase = ty * 8;
    ull acc0[8], acc1[8];
    #pragma unroll
    for (int i = 0; i < 8; i++) { acc0[i] = 0ull; acc1[i] = 0ull; }

    #pragma unroll 2
    for (int ci = 0; ci < 80; ci++) {
        ull px[10];
        #pragma unroll
        for (int r = 0; r < 10; r++) px[r] = pack2(sx[rbase + r][ci]);
        #pragma unroll
        for (int k = 0; k < 3; k++) {
            const float* wp = g_w1t + (k * 400 + ci) * 128 + 2 * lane;
            ull w0 = *(const ull*)wp;
            ull w1 = *(const ull*)(wp + 64);
            #pragma unroll
            for (int tt = 0; tt < 8; tt++) {
                fma2(acc0[tt], px[tt + k], w0);
                fma2(acc1[tt], px[tt + k], w1);
            }
        }
    }

    float2 bz0 = *(const float2*)(bias + 2 * lane);
    float2 bz1 = *(const float2*)(bias + 64 + 2 * lane);
    #pragma unroll
    for (int tt = 0; tt < 8; tt++) {
        int t = t0 + rbase + tt;
        float2 a0 = unpack2(acc0[tt]); a0.x += bz0.x; a0.y += bz0.y;
        float2 a1 = unpack2(acc1[tt]); a1.x += bz1.x; a1.y += bz1.y;
        #pragma unroll
        for (int k = 0; k < 3; k++) {
            int tp = t + k - 1;
            if (tp >= 0 && tp < T_) {
                const float* gp = g_gpart + (b * 3 + k) * 128 + 2 * lane;
                const float* st = g_sty + ((b * 80 + sch[rbase + tt + k]) * 3 + k) * 128 + 2 * lane;
                float2 g0 = *(const float2*)gp,        g1 = *(const float2*)(gp + 64);
                float2 s0 = *(const float2*)st,        s1 = *(const float2*)(st + 64);
                a0.x += g0.x + s0.x; a0.y += g0.y + s0.y;
                a1.x += g1.x + s1.x; a1.y += g1.y + s1.y;
            }
        }
        float* o = g_x1 + (b * T_ + t) * 128 + 2 * lane;
        *(float2*)o = a0;
        *(float2*)(o + 64) = a1;
    }
}

// ---------------- GN stats -> fused affine, coalesced ----------------
template<int C, int G, int WHICH>
__global__ void stats_k(const float* __restrict__ gs, const float* __restrict__ gb) {
    const float* x = (WHICH == 1) ? g_x1 : (WHICH == 2) ? g_x2 : g_x3;
    float* ab = (WHICH == 1) ? g_ab1 : (WHICH == 2) ? g_ab2 : g_ab3;
    float* dd = (WHICH == 1) ? g_dd1 : (WHICH == 2) ? g_dd2 : g_dd3;
    int b = blockIdx.x;
    int tid = threadIdx.x;              // 512 threads
    int c = tid % C;
    int tg = tid / C;
    const int TGS = 512 / C;
    const float* p = x + b * T_ * C + c;
    float s = 0.f, q = 0.f;
    for (int t = tg; t < T_; t += TGS) {
        float v = p[t * C];
        s += v; q = fmaf(v, v, q);
    }
    __shared__ float ss[512], sq[512];
    __shared__ float sS[C], sQ[C];
    ss[tid] = s; sq[tid] = q;
    __syncthreads();
    if (tid < C) {
        float S = 0.f, Q = 0.f;
        #pragma unroll
        for (int j = 0; j < TGS; j++) { S += ss[j * C + c]; Q += sq[j * C + c]; }
        sS[c] = S; sQ[c] = Q;
    }
    __syncthreads();
    if (tid < C) {
        int g0 = (c / G) * G;
        float S = 0.f, Q = 0.f;
        #pragma unroll
        for (int j = 0; j < G; j++) { S += sS[g0 + j]; Q += sQ[g0 + j]; }
        float n = (float)(G * T_);
        float mu = S / n;
        float var = Q / n - mu * mu;
        float a = rsqrtf(var + 1e-5f) * gs[c];
        ab[b * C + c] = a;
        dd[b * C + c] = gb[c] - mu * a;
    }
}

// ---------------- conv2: 128->64, FFMA2, GN1+relu on smem load ----------------
__global__ __launch_bounds__(256) void conv2_k(const float* __restrict__ bias) {
    int b = blockIdx.y;
    int t0 = blockIdx.x * 64;
    int lane = threadIdx.x;     // copair 0..31 (co = 2*lane)
    int ty = threadIdx.y;       // 0..7
    __shared__ float sx[66][128];
    int tid = ty * 32 + lane;
    const float* ab = g_ab1 + b * 128;
    const float* dd = g_dd1 + b * 128;
    for (int i = tid; i < 66 * 128; i += 256) {
        int r = i >> 7, ci = i & 127;
        int t = t0 - 1 + r;
        float v = 0.f;
        if (t >= 0 && t < T_)
            v = fmaxf(fmaf(ab[ci], g_x1[(b * T_ + t) * 128 + ci], dd[ci]), 0.f);
        sx[r][ci] = v;
    }
    __syncthreads();

    int rbase = ty * 8;
    ull acc[8];
    #pragma unroll
    for (int i = 0; i < 8; i++) acc[i] = 0ull;

    #pragma unroll 2
    for (int ci = 0; ci < 128; ci++) {
        ull px[10];
        #pragma unroll
        for (int r = 0; r < 10; r++) px[r] = pack2(sx[rbase + r][ci]);
        #pragma unroll
        for (int k = 0; k < 3; k++) {
            ull w = *(const ull*)(g_w2t + (k * 128 + ci) * 64 + 2 * lane);
            #pragma unroll
            for (int tt = 0; tt < 8; tt++) fma2(acc[tt], px[tt + k], w);
        }
    }

    float2 bz = *(const float2*)(bias + 2 * lane);
    #pragma unroll
    for (int tt = 0; tt < 8; tt++) {
        int t = t0 + rbase + tt;
        float2 a = unpack2(acc[tt]); a.x += bz.x; a.y += bz.y;
        *(float2*)(g_x2 + (b * T_ + t) * 64 + 2 * lane) = a;
    }
}

// ---------------- conv3: 64->32, FFMA2 ----------------
__global__ __launch_bounds__(256) void conv3_k(const float* __restrict__ bias) {
    int b = blockIdx.y;
    int t0 = blockIdx.x * 128;
    int lane = threadIdx.x;
    int cp = lane & 15;          // co = 2*cp
    int sub = lane >> 4;
    int ty = threadIdx.y;        // 0..7
    __shared__ float sx[130][64];
    int tid = ty * 32 + lane;
    const float* ab = g_ab2 + b * 64;
    const float* dd = g_dd2 + b * 64;
    for (int i = tid; i < 130 * 64; i += 256) {
        int r = i >> 6, ci = i & 63;
        int t = t0 - 1 + r;
        float v = 0.f;
        if (t >= 0 && t < T_)
            v = fmaxf(fmaf(ab[ci], g_x2[(b * T_ + t) * 64 + ci], dd[ci]), 0.f);
        sx[r][ci] = v;
    }
    __syncthreads();

    int rbase = (ty * 2 + sub) * 8;
    ull acc[8];
    #pragma unroll
    for (int i = 0; i < 8; i++) acc[i] = 0ull;

    #pragma unroll 2
    for (int ci = 0; ci < 64; ci++) {
        ull px[10];
        #pragma unroll
        for (int r = 0; r < 10; r++) px[r] = pack2(sx[rbase + r][ci]);
        #pragma unroll
        for (int k = 0; k < 3; k++) {
            ull w = *(const ull*)(g_w3t + (k * 64 + ci) * 32 + 2 * cp);
            #pragma unroll
            for (int tt = 0; tt < 8; tt++) fma2(acc[tt], px[tt + k], w);
        }
    }

    float2 bz = *(const float2*)(bias + 2 * cp);
    #pragma unroll
    for (int tt = 0; tt < 8; tt++) {
        int t = t0 + rbase + tt;
        float2 a = unpack2(acc[tt]); a.x += bz.x; a.y += bz.y;
        *(float2*)(g_x3 + (b * T_ + t) * 32 + 2 * cp) = a;
    }
}

// ---------------- final: GN3+relu + 1x1 conv + affine, warp per t ----------------
__global__ void final_k(const float* __restrict__ w4, const float* __restrict__ b4,
                        const float* __restrict__ mean, const float* __restrict__ stdv,
                        float* __restrict__ out) {
    int b = blockIdx.y;
    int w = threadIdx.x >> 5, lane = threadIdx.x & 31;
    float wv = w4[lane];
    float a = g_ab3[b * 32 + lane], d0 = g_dd3[b * 32 + lane];
    float bb = b4[0], me = mean[0], sc = stdv[0];
    int tbase = blockIdx.x * 128 + w * 16;
    for (int i = 0; i < 16; i++) {
        int t = tbase + i;
        float v = fmaxf(fmaf(a, g_x3[(b * T_ + t) * 32 + lane], d0), 0.f) * wv;
        #pragma unroll
        for (int off = 16; off; off >>= 1) v += __shfl_xor_sync(0xFFFFFFFFu, v, off);
        if (lane == 0) out[t * B_ + b] = fmaf(v + bb, sc, me);
    }
}

// ---------------- launcher ----------------
extern "C" void kernel_launch(void* const* d_in, const int* in_sizes, int n_in,
                              void* d_out, int out_size) {
    (void)in_sizes; (void)n_in; (void)out_size;
    const float* input      = (const float*)d_in[0];
    const float* g_style    = (const float*)d_in[1];
    const float* char_style = (const float*)d_in[3];
    const float* w1 = (const float*)d_in[4];
    const float* b1 = (const float*)d_in[5];
    const float* gs1 = (const float*)d_in[6];
    const float* gb1 = (const float*)d_in[7];
    const float* w2 = (const float*)d_in[8];
    const float* b2 = (const float*)d_in[9];
    const float* gs2 = (const float*)d_in[10];
    const float* gb2 = (const float*)d_in[11];
    const float* w3 = (const float*)d_in[12];
    const float* b3 = (const float*)d_in[13];
    const float* gs3 = (const float*)d_in[14];
    const float* gb3 = (const float*)d_in[15];
    const float* w4 = (const float*)d_in[16];
    const float* b4 = (const float*)d_in[17];
    const float* mean = (const float*)d_in[18];
    const float* stdv = (const float*)d_in[19];
    float* out = (float*)d_out;

    wtrans_k<<<(128 * 400 * 3 + 255) / 256, 256>>>(w1, 128, 400, 0);
    wtrans_k<<<(64 * 128 * 3 + 255) / 256, 256>>>(w2, 64, 128, 1);
    wtrans_k<<<(32 * 64 * 3 + 255) / 256, 256>>>(w3, 32, 64, 2);
    argmax_k<<<(T_ * B_ * 32) / 256, 256>>>(input);
    stylepre_k<<<dim3(3, B_), 128>>>(char_style);
    gpart_k<<<B_, 128>>>(g_style);
    conv1_k<<<dim3(T_ / 64, B_), dim3(32, 8)>>>(input, b1);
    stats_k<128, 4, 1><<<B_, 512>>>(gs1, gb1);
    conv2_k<<<dim3(T_ / 64, B_), dim3(32, 8)>>>(b2);
    stats_k<64, 2, 2><<<B_, 512>>>(gs2, gb2);
    conv3_k<<<dim3(T_ / 128, B_), dim3(32, 8)>>>(b3);
    stats_k<32, 1, 3><<<B_, 512>>>(gs3, gb3);
    final_k<<<dim3(T_ / 128, B_), 256>>>(w4, b4, mean, stdv, out);
}